// round 6
// baseline (speedup 1.0000x reference)
#include <cuda_runtime.h>
#include <cuda_fp16.h>
#include <math.h>
#include <stdint.h>

// ---------------------------------------------------------------------------
// Problem constants
// ---------------------------------------------------------------------------
#define DD 1024
#define SS 2048
#define BB 2
#define MT (BB * SS)          // 4096

// ---------------------------------------------------------------------------
// Scratch (device globals; no allocation allowed)
// ---------------------------------------------------------------------------
__device__ __half g_xh[MT * DD], g_xl[MT * DD];
__device__ __half g_wt16[DD * DD];                    // wi^T fp16
__device__ float  g_w2[DD * DD];
__device__ __half g_w2t16[DD * DD];                   // W2^T fp16
__device__ float  g_q[MT * DD];
__device__ __half g_qh[MT * DD], g_ql[MT * DD];
__device__ __half g_qt16[MT * DD];                    // q^T per batch, fp16
__device__ float  g_sc[(size_t)BB * SS * SS];
__device__ __half g_ph[(size_t)BB * SS * SS];         // softmax P (fp16 hi only)
__device__ __half g_heh[MT * DD], g_hel[MT * DD];     // head hi/lo
__device__ float  g_hn[MT * DD];                      // h (pre-LN)
__device__ __half g_nh[MT * DD], g_nl[MT * DD];       // LN(h) hi/lo
__device__ __half g_th[MT * DD], g_tl[MT * DD];       // swish out hi/lo

// ---------------------------------------------------------------------------
// PTX helpers (baseline ISA only)
// ---------------------------------------------------------------------------
__device__ __forceinline__ uint32_t smem_to_u32(const void* p) {
    uint32_t a;
    asm("{ .reg .u64 t; cvta.to.shared.u64 t, %1; cvt.u32.u64 %0, t; }"
        : "=r"(a) : "l"(p));
    return a;
}
__device__ __forceinline__ void cpasync16(uint32_t dst, const void* src) {
    asm volatile("cp.async.cg.shared.global [%0], [%1], 16;" :: "r"(dst), "l"(src));
}
#define CP_COMMIT() asm volatile("cp.async.commit_group;" ::: "memory")
#define CP_WAIT(n)  asm volatile("cp.async.wait_group %0;" :: "n"(n) : "memory")

__device__ __forceinline__ void ldsm4(uint32_t* r, uint32_t addr) {
    asm volatile("ldmatrix.sync.aligned.m8n8.x4.shared.b16 {%0,%1,%2,%3}, [%4];"
                 : "=r"(r[0]), "=r"(r[1]), "=r"(r[2]), "=r"(r[3]) : "r"(addr));
}
__device__ __forceinline__ void mma16816(float* c, const uint32_t* a, const uint32_t* b) {
    asm volatile(
        "mma.sync.aligned.m16n8k16.row.col.f32.f16.f16.f32 "
        "{%0,%1,%2,%3}, {%4,%5,%6,%7}, {%8,%9}, {%0,%1,%2,%3};"
        : "+f"(c[0]), "+f"(c[1]), "+f"(c[2]), "+f"(c[3])
        : "r"(a[0]), "r"(a[1]), "r"(a[2]), "r"(a[3]), "r"(b[0]), "r"(b[1]));
}

// ---------------------------------------------------------------------------
// fp32 -> fp16 hi/lo split
// ---------------------------------------------------------------------------
__device__ __forceinline__ void split1(float v, __half& h, __half& l) {
    h = __float2half(v);
    l = __float2half(v - __half2float(h));
}

// ---------------------------------------------------------------------------
// Elementwise / reshape kernels
// ---------------------------------------------------------------------------
__global__ void split_kernel(const float* __restrict__ in,
                             __half* __restrict__ oh,
                             __half* __restrict__ ol, int n4) {
    int i = blockIdx.x * blockDim.x + threadIdx.x;
    if (i >= n4) return;
    float4 v = ((const float4*)in)[i];
    __half h, l;
    size_t b = (size_t)i * 4;
    split1(v.x, h, l); oh[b + 0] = h; ol[b + 0] = l;
    split1(v.y, h, l); oh[b + 1] = h; ol[b + 1] = l;
    split1(v.z, h, l); oh[b + 2] = h; ol[b + 2] = l;
    split1(v.w, h, l); oh[b + 3] = h; ol[b + 3] = l;
}

// out[c][r] = fp16(in[r][c]); out dims [C,R]; z-batched
__global__ void transpose_h_kernel(const float* __restrict__ in,
                                   __half* __restrict__ o16,
                                   int R, int C, long sin, long sout) {
    __shared__ float t[32][33];
    in += (size_t)blockIdx.z * sin;
    o16 += (size_t)blockIdx.z * sout;
    int r0 = blockIdx.y * 32, c0 = blockIdx.x * 32;
    for (int i = threadIdx.y; i < 32; i += 8)
        t[i][threadIdx.x] = in[(size_t)(r0 + i) * C + c0 + threadIdx.x];
    __syncthreads();
    for (int i = threadIdx.y; i < 32; i += 8) {
        size_t o = (size_t)(c0 + i) * R + r0 + threadIdx.x;
        o16[o] = __float2half(t[threadIdx.x][i]);
    }
}

__global__ void w2_reduce_kernel(const float* __restrict__ ok,
                                 float* __restrict__ w2, int H) {
    int idx = blockIdx.x * blockDim.x + threadIdx.x;
    if (idx >= DD * DD) return;
    int i = idx / DD, j = idx % DD;
    float s = 0.f;
    for (int h = 0; h < H; h++) s += ok[(size_t)(h * DD + i) * DD + j];
    w2[idx] = s;
}

// Causal softmax. One block per (batch,row). Reads cols [0, L); writes P (fp16)
// for cols [0, Kc), Kc = ceil128(L); zeros beyond L. P@V clamps K to Kc.
__global__ void softmax_kernel(const float* __restrict__ S,
                               __half* __restrict__ ph) {
    __shared__ float red[256];
    const int tid = threadIdx.x;
    const int L = (blockIdx.x & (SS - 1)) + 1;
    const int Kc = (L + 127) & ~127;
    const size_t base = (size_t)blockIdx.x * SS;

    float vals[8];
    float m = -3.0e38f;
    int n = 0;
    for (int c = tid; c < L; c += 256) {
        float v = S[base + c];
        vals[n++] = v;
        m = fmaxf(m, v);
    }
    red[tid] = m; __syncthreads();
    for (int s = 128; s > 0; s >>= 1) { if (tid < s) red[tid] = fmaxf(red[tid], red[tid + s]); __syncthreads(); }
    m = red[0]; __syncthreads();

    float sum = 0.f;
#pragma unroll 8
    for (int i = 0; i < n; i++) { vals[i] = expf(vals[i] - m); sum += vals[i]; }
    red[tid] = sum; __syncthreads();
    for (int s = 128; s > 0; s >>= 1) { if (tid < s) red[tid] += red[tid + s]; __syncthreads(); }
    float inv = 1.0f / red[0];

    n = 0;
    for (int c = tid; c < Kc; c += 256) {
        float p = (c < L) ? vals[n] * inv : 0.f;
        if (c < L) n++;
        ph[base + c] = __float2half(p);
    }
}

__global__ void layernorm_kernel(const float* __restrict__ H,
                                 __half* __restrict__ oh,
                                 __half* __restrict__ ol) {
    __shared__ float red[256];
    int tid = threadIdx.x;
    size_t base = (size_t)blockIdx.x * DD;
    float4 v = ((const float4*)(H + base))[tid];

    red[tid] = v.x + v.y + v.z + v.w; __syncthreads();
    for (int s = 128; s > 0; s >>= 1) { if (tid < s) red[tid] += red[tid + s]; __syncthreads(); }
    float mean = red[0] * (1.0f / DD); __syncthreads();
    red[tid] = v.x * v.x + v.y * v.y + v.z * v.z + v.w * v.w; __syncthreads();
    for (int s = 128; s > 0; s >>= 1) { if (tid < s) red[tid] += red[tid + s]; __syncthreads(); }
    float msq = red[0] * (1.0f / DD);
    float inv = 1.0f / sqrtf(msq - mean * mean + 1e-5f);

    __half h, l;
    size_t o = base + (size_t)tid * 4;
    split1((v.x - mean) * inv, h, l); oh[o + 0] = h; ol[o + 0] = l;
    split1((v.y - mean) * inv, h, l); oh[o + 1] = h; ol[o + 1] = l;
    split1((v.z - mean) * inv, h, l); oh[o + 2] = h; ol[o + 2] = l;
    split1((v.w - mean) * inv, h, l); oh[o + 3] = h; ol[o + 3] = l;
}

// ---------------------------------------------------------------------------
// HMMA fp16 split GEMM: C[z] = A[z] @ B[z]^T  (A:[M,K], B:[N,K])
// NPROD=2: A hi/lo split, B single fp16 -> ah*b + al*b   (err ~2^-22 + b-round)
// NPROD=1: A single fp16, B single fp16 -> ah*b          (err ~2^-11 terms)
// Tensor slots per stage: NPROD A-tiles then 1 B-tile.
// 128x128 block tile, BK=32, 8 warps (4M x 2N), warp tile 32x64, 3-stage pipe.
// ---------------------------------------------------------------------------
enum { EPI_F32 = 0, EPI_QOUT = 1, EPI_SCORES = 2, EPI_RESID = 3, EPI_BIAS = 4, EPI_SWISH = 5 };

#define LDS_T 40                        // smem row stride (halves): conflict-free ldmatrix
#define TEN_B (128 * LDS_T * 2)         // one tensor tile: 10240 B
#define STAGES 3

__device__ __forceinline__ void load_tensor(uint32_t sdst, const __half* g,
                                            int base_row, int ldK, int kofs, int tid) {
#pragma unroll
    for (int i = 0; i < 2; i++) {
        int v = tid * 2 + i;                 // 0..511
        int row = v >> 2, cseg = v & 3;
        uint32_t dst = sdst + (uint32_t)(row * LDS_T + cseg * 8) * 2;
        cpasync16(dst, g + (size_t)(base_row + row) * ldK + kofs + cseg * 8);
    }
}

template <int EPI, bool CAUSAL, bool KCLAMP, int NPROD>
__global__ __launch_bounds__(256, 1) void gemm_tc(
    int M, int N, int K,
    const __half* __restrict__ Ah, const __half* __restrict__ Al,
    const __half* __restrict__ Bh,
    float* __restrict__ Cf,
    __half* __restrict__ Ch, __half* __restrict__ Cl,
    const float* __restrict__ Ef, float scale,
    long sA, long sB, long sC) {
    extern __shared__ char smem[];
    constexpr int NSLOT = NPROD + 1;
    constexpr uint32_t BUF_B = NSLOT * TEN_B;
    const int tid = threadIdx.x;
    const int rowStart = blockIdx.y * 128, colStart = blockIdx.x * 128;
    const int z = blockIdx.z;

    // Fully masked score tile: nothing to do (softmax never reads it).
    if (CAUSAL && colStart > rowStart) return;

    Ah += (size_t)z * sA;
    if (NPROD == 2) Al += (size_t)z * sA;
    Bh += (size_t)z * sB;
    const size_t cofs = (size_t)z * sC;

    const uint32_t sb = smem_to_u32(smem);
    const int lane = tid & 31, wid = tid >> 5;
    const int warp_m = wid & 3, warp_n = wid >> 2;

    const int NC = (KCLAMP ? (rowStart + 128) : K) / 32;

    const int a_row = warp_m * 32 + (lane & 15);
    const int a_col = (lane >> 4) * 8;
    const int b_row = warp_n * 64 + (lane & 7) + ((lane >> 4) & 1) * 8;
    const int b_col = ((lane >> 3) & 1) * 8;

    float acc[2][8][4];
#pragma unroll
    for (int i = 0; i < 2; i++)
#pragma unroll
        for (int j = 0; j < 8; j++)
#pragma unroll
            for (int q = 0; q < 4; q++) acc[i][j][q] = 0.f;

    // prologue: stages 0, 1
    {
        load_tensor(sb + 0 * TEN_B, Ah, rowStart, K, 0, tid);
        if (NPROD == 2) load_tensor(sb + 1 * TEN_B, Al, rowStart, K, 0, tid);
        load_tensor(sb + (NSLOT - 1) * TEN_B, Bh, colStart, K, 0, tid);
        CP_COMMIT();
        if (NC > 1) {
            load_tensor(sb + BUF_B + 0 * TEN_B, Ah, rowStart, K, 32, tid);
            if (NPROD == 2) load_tensor(sb + BUF_B + 1 * TEN_B, Al, rowStart, K, 32, tid);
            load_tensor(sb + BUF_B + (NSLOT - 1) * TEN_B, Bh, colStart, K, 32, tid);
            CP_COMMIT();
        }
    }

    int bufIdx = 0;
    for (int c = 0; c < NC; c++) {
        if (c + 1 < NC) { CP_WAIT(1); } else { CP_WAIT(0); }
        __syncthreads();

        if (c + 2 < NC) {
            int nIdx = bufIdx + 2; if (nIdx >= STAGES) nIdx -= STAGES;
            const uint32_t nbuf = sb + (uint32_t)nIdx * BUF_B;
            const int kofs = (c + 2) * 32;
            load_tensor(nbuf + 0 * TEN_B, Ah, rowStart, K, kofs, tid);
            if (NPROD == 2) load_tensor(nbuf + 1 * TEN_B, Al, rowStart, K, kofs, tid);
            load_tensor(nbuf + (NSLOT - 1) * TEN_B, Bh, colStart, K, kofs, tid);
            CP_COMMIT();
        }

        const uint32_t buf = sb + (uint32_t)bufIdx * BUF_B;
#pragma unroll
        for (int k0 = 0; k0 < 32; k0 += 16) {
            uint32_t ah[2][4], al[2][4], bh[4][4];
#pragma unroll
            for (int mt = 0; mt < 2; mt++) {
                uint32_t ao = (uint32_t)((a_row + mt * 16) * LDS_T + k0 + a_col) * 2;
                ldsm4(ah[mt], buf + 0 * TEN_B + ao);
                if (NPROD == 2) ldsm4(al[mt], buf + 1 * TEN_B + ao);
            }
#pragma unroll
            for (int np = 0; np < 4; np++) {
                uint32_t bo = (uint32_t)((b_row + np * 16) * LDS_T + k0 + b_col) * 2;
                ldsm4(bh[np], buf + (NSLOT - 1) * TEN_B + bo);
            }
            // pass 1: ah * bh
#pragma unroll
            for (int mt = 0; mt < 2; mt++)
#pragma unroll
                for (int np = 0; np < 4; np++) {
                    mma16816(acc[mt][2 * np + 0], ah[mt], &bh[np][0]);
                    mma16816(acc[mt][2 * np + 1], ah[mt], &bh[np][2]);
                }
            // pass 2: al * bh
            if (NPROD == 2) {
#pragma unroll
                for (int mt = 0; mt < 2; mt++)
#pragma unroll
                    for (int np = 0; np < 4; np++) {
                        mma16816(acc[mt][2 * np + 0], al[mt], &bh[np][0]);
                        mma16816(acc[mt][2 * np + 1], al[mt], &bh[np][2]);
                    }
            }
        }
        bufIdx++; if (bufIdx >= STAGES) bufIdx = 0;
    }

    // epilogue: registers -> gmem
#pragma unroll
    for (int mt = 0; mt < 2; mt++)
#pragma unroll
        for (int nt = 0; nt < 8; nt++) {
            const float* a = acc[mt][nt];
            int r0 = rowStart + warp_m * 32 + mt * 16 + (lane >> 2);
            int c0 = colStart + warp_n * 64 + nt * 8 + (lane & 3) * 2;
#pragma unroll
            for (int half = 0; half < 2; half++) {
                int gr = r0 + half * 8;
                float x0 = a[half * 2 + 0], x1 = a[half * 2 + 1];
                size_t o = cofs + (size_t)gr * N + c0;
                if (EPI == EPI_F32) {
                    *(float2*)(Cf + o) = make_float2(x0, x1);
                } else if (EPI == EPI_QOUT) {
                    *(float2*)(Cf + o) = make_float2(x0, x1);
                    __half h0, l0, h1, l1;
                    split1(x0, h0, l0); split1(x1, h1, l1);
                    *(__half2*)(Ch + o) = __halves2half2(h0, h1);
                    *(__half2*)(Cl + o) = __halves2half2(l0, l1);
                } else if (EPI == EPI_SCORES) {
                    // masked entries (col > row) may be garbage; never read.
                    *(float2*)(Cf + o) = make_float2(x0 * scale, x1 * scale);
                } else if (EPI == EPI_RESID) {
                    float2 e = *(const float2*)(Ef + o);
                    x0 += e.x; x1 += e.y;
                    __half h0, l0, h1, l1;
                    split1(x0, h0, l0); split1(x1, h1, l1);
                    *(__half2*)(Ch + o) = __halves2half2(h0, h1);
                    *(__half2*)(Cl + o) = __halves2half2(l0, l1);
                } else if (EPI == EPI_BIAS) {
                    x0 += Ef[c0]; x1 += Ef[c0 + 1];
                    *(float2*)(Cf + o) = make_float2(x0, x1);
                } else if (EPI == EPI_SWISH) {
                    x0 = x0 / (1.f + expf(-x0));
                    x1 = x1 / (1.f + expf(-x1));
                    __half h0, l0, h1, l1;
                    split1(x0, h0, l0); split1(x1, h1, l1);
                    *(__half2*)(Ch + o) = __halves2half2(h0, h1);
                    *(__half2*)(Cl + o) = __halves2half2(l0, l1);
                }
            }
        }
}

// ---------------------------------------------------------------------------
extern "C" void kernel_launch(void* const* d_in, const int* in_sizes, int n_in,
                              void* d_out, int out_size) {
    const float* x    = (const float*)d_in[0];
    const float* wi   = (const float*)d_in[2];
    const float* ok   = (const float*)d_in[3];
    const float* bias = (const float*)d_in[4];
    float* out = (float*)d_out;
    int H = in_sizes[3] / (DD * DD);

    float *q, *w2, *sc, *hn;
    __half *xh, *xl, *wt16, *w2t16, *qh, *ql, *qt16;
    __half *pph, *heh, *hel, *nh, *nl, *th, *tl;
    cudaGetSymbolAddress((void**)&q,     g_q);
    cudaGetSymbolAddress((void**)&w2,    g_w2);
    cudaGetSymbolAddress((void**)&sc,    g_sc);
    cudaGetSymbolAddress((void**)&hn,    g_hn);
    cudaGetSymbolAddress((void**)&xh,    g_xh);    cudaGetSymbolAddress((void**)&xl,   g_xl);
    cudaGetSymbolAddress((void**)&wt16,  g_wt16);
    cudaGetSymbolAddress((void**)&w2t16, g_w2t16);
    cudaGetSymbolAddress((void**)&qh,    g_qh);    cudaGetSymbolAddress((void**)&ql,   g_ql);
    cudaGetSymbolAddress((void**)&qt16,  g_qt16);
    cudaGetSymbolAddress((void**)&pph,   g_ph);
    cudaGetSymbolAddress((void**)&heh,   g_heh);   cudaGetSymbolAddress((void**)&hel,  g_hel);
    cudaGetSymbolAddress((void**)&nh,    g_nh);    cudaGetSymbolAddress((void**)&nl,   g_nl);
    cudaGetSymbolAddress((void**)&th,    g_th);    cudaGetSymbolAddress((void**)&tl,   g_tl);

    const int SM3 = STAGES * 3 * TEN_B;   // NPROD=2 kernels: 92160 B
    const int SM2 = STAGES * 2 * TEN_B;   // NPROD=1 kernels: 61440 B

    cudaFuncSetAttribute((const void*)gemm_tc<EPI_QOUT,   false, false, 2>, cudaFuncAttributeMaxDynamicSharedMemorySize, SM3);
    cudaFuncSetAttribute((const void*)gemm_tc<EPI_SCORES, true,  false, 2>, cudaFuncAttributeMaxDynamicSharedMemorySize, SM3);
    cudaFuncSetAttribute((const void*)gemm_tc<EPI_RESID,  false, true,  1>, cudaFuncAttributeMaxDynamicSharedMemorySize, SM2);
    cudaFuncSetAttribute((const void*)gemm_tc<EPI_BIAS,   false, false, 2>, cudaFuncAttributeMaxDynamicSharedMemorySize, SM3);
    cudaFuncSetAttribute((const void*)gemm_tc<EPI_SWISH,  false, false, 2>, cudaFuncAttributeMaxDynamicSharedMemorySize, SM3);
    cudaFuncSetAttribute((const void*)gemm_tc<EPI_F32,    false, false, 2>, cudaFuncAttributeMaxDynamicSharedMemorySize, SM3);

    // --- preprocessing ---
    split_kernel<<<(MT * DD / 4 + 255) / 256, 256>>>(x, xh, xl, MT * DD / 4);
    transpose_h_kernel<<<dim3(32, 32, 1), dim3(32, 8)>>>(wi, wt16, DD, DD, 0, 0);
    w2_reduce_kernel<<<(DD * DD + 255) / 256, 256>>>(ok, w2, H);
    transpose_h_kernel<<<dim3(32, 32, 1), dim3(32, 8)>>>(w2, w2t16, DD, DD, 0, 0);

    // q = x @ wi  (A split, B = wi^T fp16)  -> q fp32 + hi/lo
    gemm_tc<EPI_QOUT, false, false, 2><<<dim3(DD / 128, MT / 128, 1), 256, SM3>>>(
        MT, DD, DD, xh, xl, wt16, q, qh, ql, nullptr, 0.f, 0, 0, 0);

    // q^T per batch (single fp16, B operand for P@V)
    transpose_h_kernel<<<dim3(32, 64, BB), dim3(32, 8)>>>(
        q, qt16, SS, DD, (long)SS * DD, (long)SS * DD);

    // scores = (q @ q^T)/32  — A split, B = qh single (2 products), tri-skip
    gemm_tc<EPI_SCORES, true, false, 2><<<dim3(SS / 128, SS / 128, BB), 256, SM3>>>(
        SS, SS, DD, qh, ql, qh, sc, nullptr, nullptr, nullptr, 1.0f / 32.0f,
        (long)SS * DD, (long)SS * DD, (long)SS * SS);

    // causal softmax -> P fp16 (zeros to 128-padded boundary)
    softmax_kernel<<<BB * SS, 256>>>(sc, pph);

    // head = q + P @ q   (single product: P16 x q16^T, causal K clamp)
    gemm_tc<EPI_RESID, false, true, 1><<<dim3(DD / 128, SS / 128, BB), 256, SM2>>>(
        SS, DD, SS, pph, nullptr, qt16, nullptr, heh, hel, q, 0.f,
        (long)SS * SS, (long)SS * DD, (long)SS * DD);

    // h = head @ W2 + bias -> fp32
    gemm_tc<EPI_BIAS, false, false, 2><<<dim3(DD / 128, MT / 128, 1), 256, SM3>>>(
        MT, DD, DD, heh, hel, w2t16, hn, nullptr, nullptr, bias, 0.f, 0, 0, 0);

    // LayerNorm -> hi/lo
    layernorm_kernel<<<MT, 256>>>(hn, nh, nl);

    // t = swish(h @ wi) -> hi/lo
    gemm_tc<EPI_SWISH, false, false, 2><<<dim3(DD / 128, MT / 128, 1), 256, SM3>>>(
        MT, DD, DD, nh, nl, wt16, nullptr, th, tl, nullptr, 0.f, 0, 0, 0);

    // out = t @ wi -> fp32
    gemm_tc<EPI_F32, false, false, 2><<<dim3(DD / 128, MT / 128, 1), 256, SM3>>>(
        MT, DD, DD, th, tl, wt16, out, nullptr, nullptr, nullptr, 0.f, 0, 0, 0);
}

// round 7
// speedup vs baseline: 1.0560x; 1.0560x over previous
#include <cuda_runtime.h>
#include <cuda_fp16.h>
#include <math.h>
#include <stdint.h>

// ---------------------------------------------------------------------------
// Problem constants
// ---------------------------------------------------------------------------
#define DD 1024
#define SS 2048
#define BB 2
#define MT (BB * SS)          // 4096

// ---------------------------------------------------------------------------
// Scratch (device globals; no allocation allowed)
// ---------------------------------------------------------------------------
__device__ __half g_xh[MT * DD], g_xl[MT * DD];
__device__ __half g_wt16[DD * DD];                    // wi^T fp16
__device__ float  g_w2[DD * DD];
__device__ __half g_w2t16[DD * DD];                   // W2^T fp16
__device__ float  g_q[MT * DD];
__device__ __half g_qh[MT * DD], g_ql[MT * DD];
__device__ __half g_qt16[MT * DD];                    // q^T per batch, fp16
__device__ float  g_sc[(size_t)BB * SS * SS];
__device__ __half g_ph[(size_t)BB * SS * SS];         // softmax P (fp16 hi only)
__device__ __half g_heh[MT * DD], g_hel[MT * DD];     // head hi/lo
__device__ float  g_hn[MT * DD];                      // h (pre-LN)
__device__ __half g_nh[MT * DD], g_nl[MT * DD];       // LN(h) hi/lo
__device__ __half g_th[MT * DD], g_tl[MT * DD];       // swish out hi/lo

// ---------------------------------------------------------------------------
// PTX helpers (baseline ISA only)
// ---------------------------------------------------------------------------
__device__ __forceinline__ uint32_t smem_to_u32(const void* p) {
    uint32_t a;
    asm("{ .reg .u64 t; cvta.to.shared.u64 t, %1; cvt.u32.u64 %0, t; }"
        : "=r"(a) : "l"(p));
    return a;
}
__device__ __forceinline__ void cpasync16(uint32_t dst, const void* src) {
    asm volatile("cp.async.cg.shared.global [%0], [%1], 16;" :: "r"(dst), "l"(src));
}
#define CP_COMMIT() asm volatile("cp.async.commit_group;" ::: "memory")
#define CP_WAIT(n)  asm volatile("cp.async.wait_group %0;" :: "n"(n) : "memory")

__device__ __forceinline__ void ldsm4(uint32_t* r, uint32_t addr) {
    asm volatile("ldmatrix.sync.aligned.m8n8.x4.shared.b16 {%0,%1,%2,%3}, [%4];"
                 : "=r"(r[0]), "=r"(r[1]), "=r"(r[2]), "=r"(r[3]) : "r"(addr));
}
__device__ __forceinline__ void mma16816(float* c, const uint32_t* a, const uint32_t* b) {
    asm volatile(
        "mma.sync.aligned.m16n8k16.row.col.f32.f16.f16.f32 "
        "{%0,%1,%2,%3}, {%4,%5,%6,%7}, {%8,%9}, {%0,%1,%2,%3};"
        : "+f"(c[0]), "+f"(c[1]), "+f"(c[2]), "+f"(c[3])
        : "r"(a[0]), "r"(a[1]), "r"(a[2]), "r"(a[3]), "r"(b[0]), "r"(b[1]));
}

// ---------------------------------------------------------------------------
// fp32 -> fp16 hi/lo split
// ---------------------------------------------------------------------------
__device__ __forceinline__ void split1(float v, __half& h, __half& l) {
    h = __float2half(v);
    l = __float2half(v - __half2float(h));
}

// ---------------------------------------------------------------------------
// Elementwise / reshape kernels
// ---------------------------------------------------------------------------
__global__ void split_kernel(const float* __restrict__ in,
                             __half* __restrict__ oh,
                             __half* __restrict__ ol, int n4) {
    int i = blockIdx.x * blockDim.x + threadIdx.x;
    if (i >= n4) return;
    float4 v = ((const float4*)in)[i];
    __half h, l;
    size_t b = (size_t)i * 4;
    split1(v.x, h, l); oh[b + 0] = h; ol[b + 0] = l;
    split1(v.y, h, l); oh[b + 1] = h; ol[b + 1] = l;
    split1(v.z, h, l); oh[b + 2] = h; ol[b + 2] = l;
    split1(v.w, h, l); oh[b + 3] = h; ol[b + 3] = l;
}

// out[c][r] = fp16(in[r][c]); out dims [C,R]; z-batched
__global__ void transpose_h_kernel(const float* __restrict__ in,
                                   __half* __restrict__ o16,
                                   int R, int C, long sin, long sout) {
    __shared__ float t[32][33];
    in += (size_t)blockIdx.z * sin;
    o16 += (size_t)blockIdx.z * sout;
    int r0 = blockIdx.y * 32, c0 = blockIdx.x * 32;
    for (int i = threadIdx.y; i < 32; i += 8)
        t[i][threadIdx.x] = in[(size_t)(r0 + i) * C + c0 + threadIdx.x];
    __syncthreads();
    for (int i = threadIdx.y; i < 32; i += 8) {
        size_t o = (size_t)(c0 + i) * R + r0 + threadIdx.x;
        o16[o] = __float2half(t[threadIdx.x][i]);
    }
}

__global__ void w2_reduce_kernel(const float* __restrict__ ok,
                                 float* __restrict__ w2, int H) {
    int idx = blockIdx.x * blockDim.x + threadIdx.x;
    if (idx >= DD * DD) return;
    int i = idx / DD, j = idx % DD;
    float s = 0.f;
    for (int h = 0; h < H; h++) s += ok[(size_t)(h * DD + i) * DD + j];
    w2[idx] = s;
}

// Causal softmax. One block per (batch,row). Reads cols [0, L); writes P (fp16)
// for cols [0, Kc), Kc = ceil128(L); zeros beyond L. P@V clamps K to Kc.
__global__ void softmax_kernel(const float* __restrict__ S,
                               __half* __restrict__ ph) {
    __shared__ float red[256];
    const int tid = threadIdx.x;
    const int L = (blockIdx.x & (SS - 1)) + 1;
    const int Kc = (L + 127) & ~127;
    const size_t base = (size_t)blockIdx.x * SS;

    float vals[8];
    float m = -3.0e38f;
    int n = 0;
    for (int c = tid; c < L; c += 256) {
        float v = S[base + c];
        vals[n++] = v;
        m = fmaxf(m, v);
    }
    red[tid] = m; __syncthreads();
    for (int s = 128; s > 0; s >>= 1) { if (tid < s) red[tid] = fmaxf(red[tid], red[tid + s]); __syncthreads(); }
    m = red[0]; __syncthreads();

    float sum = 0.f;
#pragma unroll 8
    for (int i = 0; i < n; i++) { vals[i] = expf(vals[i] - m); sum += vals[i]; }
    red[tid] = sum; __syncthreads();
    for (int s = 128; s > 0; s >>= 1) { if (tid < s) red[tid] += red[tid + s]; __syncthreads(); }
    float inv = 1.0f / red[0];

    n = 0;
    for (int c = tid; c < Kc; c += 256) {
        float p = (c < L) ? vals[n] * inv : 0.f;
        if (c < L) n++;
        ph[base + c] = __float2half(p);
    }
}

__global__ void layernorm_kernel(const float* __restrict__ H,
                                 __half* __restrict__ oh,
                                 __half* __restrict__ ol) {
    __shared__ float red[256];
    int tid = threadIdx.x;
    size_t base = (size_t)blockIdx.x * DD;
    float4 v = ((const float4*)(H + base))[tid];

    red[tid] = v.x + v.y + v.z + v.w; __syncthreads();
    for (int s = 128; s > 0; s >>= 1) { if (tid < s) red[tid] += red[tid + s]; __syncthreads(); }
    float mean = red[0] * (1.0f / DD); __syncthreads();
    red[tid] = v.x * v.x + v.y * v.y + v.z * v.z + v.w * v.w; __syncthreads();
    for (int s = 128; s > 0; s >>= 1) { if (tid < s) red[tid] += red[tid + s]; __syncthreads(); }
    float msq = red[0] * (1.0f / DD);
    float inv = 1.0f / sqrtf(msq - mean * mean + 1e-5f);

    __half h, l;
    size_t o = base + (size_t)tid * 4;
    split1((v.x - mean) * inv, h, l); oh[o + 0] = h; ol[o + 0] = l;
    split1((v.y - mean) * inv, h, l); oh[o + 1] = h; ol[o + 1] = l;
    split1((v.z - mean) * inv, h, l); oh[o + 2] = h; ol[o + 2] = l;
    split1((v.w - mean) * inv, h, l); oh[o + 3] = h; ol[o + 3] = l;
}

// ---------------------------------------------------------------------------
// HMMA fp16 split GEMM: C[z] = A[z] @ B[z]^T  (A:[M,K], B:[N,K])
// NPROD=2: A hi/lo split, B single fp16 -> ah*b + al*b
// NPROD=1: A single fp16, B single fp16 -> ah*b
// 128x128 block tile, BK=32, 8 warps (4M x 2N), warp tile 32x64, 3-stage pipe.
// __launch_bounds__(256, 2): cap regs at 128 so 2 CTAs co-reside per SM and
// hide the per-chunk __syncthreads/CP_WAIT latency that bound earlier rounds.
// ---------------------------------------------------------------------------
enum { EPI_F32 = 0, EPI_QOUT = 1, EPI_SCORES = 2, EPI_RESID = 3, EPI_BIAS = 4, EPI_SWISH = 5 };

#define LDS_T 40                        // smem row stride (halves): conflict-free ldmatrix
#define TEN_B (128 * LDS_T * 2)         // one tensor tile: 10240 B
#define STAGES 3

__device__ __forceinline__ void load_tensor(uint32_t sdst, const __half* g,
                                            int base_row, int ldK, int kofs, int tid) {
#pragma unroll
    for (int i = 0; i < 2; i++) {
        int v = tid * 2 + i;                 // 0..511
        int row = v >> 2, cseg = v & 3;
        uint32_t dst = sdst + (uint32_t)(row * LDS_T + cseg * 8) * 2;
        cpasync16(dst, g + (size_t)(base_row + row) * ldK + kofs + cseg * 8);
    }
}

template <int EPI, bool CAUSAL, bool KCLAMP, int NPROD>
__global__ __launch_bounds__(256, 2) void gemm_tc(
    int M, int N, int K,
    const __half* __restrict__ Ah, const __half* __restrict__ Al,
    const __half* __restrict__ Bh,
    float* __restrict__ Cf,
    __half* __restrict__ Ch, __half* __restrict__ Cl,
    const float* __restrict__ Ef, float scale,
    long sA, long sB, long sC) {
    extern __shared__ char smem[];
    constexpr int NSLOT = NPROD + 1;
    constexpr uint32_t BUF_B = NSLOT * TEN_B;
    const int tid = threadIdx.x;
    const int rowStart = blockIdx.y * 128, colStart = blockIdx.x * 128;
    const int z = blockIdx.z;

    // Fully masked score tile: nothing to do (softmax never reads it).
    if (CAUSAL && colStart > rowStart) return;

    Ah += (size_t)z * sA;
    if (NPROD == 2) Al += (size_t)z * sA;
    Bh += (size_t)z * sB;
    const size_t cofs = (size_t)z * sC;

    const uint32_t sb = smem_to_u32(smem);
    const int lane = tid & 31, wid = tid >> 5;
    const int warp_m = wid & 3, warp_n = wid >> 2;

    const int NC = (KCLAMP ? (rowStart + 128) : K) / 32;

    const int a_row = warp_m * 32 + (lane & 15);
    const int a_col = (lane >> 4) * 8;
    const int b_row = warp_n * 64 + (lane & 7) + ((lane >> 4) & 1) * 8;
    const int b_col = ((lane >> 3) & 1) * 8;

    float acc[2][8][4];
#pragma unroll
    for (int i = 0; i < 2; i++)
#pragma unroll
        for (int j = 0; j < 8; j++)
#pragma unroll
            for (int q = 0; q < 4; q++) acc[i][j][q] = 0.f;

    // prologue: stages 0, 1
    {
        load_tensor(sb + 0 * TEN_B, Ah, rowStart, K, 0, tid);
        if (NPROD == 2) load_tensor(sb + 1 * TEN_B, Al, rowStart, K, 0, tid);
        load_tensor(sb + (NSLOT - 1) * TEN_B, Bh, colStart, K, 0, tid);
        CP_COMMIT();
        if (NC > 1) {
            load_tensor(sb + BUF_B + 0 * TEN_B, Ah, rowStart, K, 32, tid);
            if (NPROD == 2) load_tensor(sb + BUF_B + 1 * TEN_B, Al, rowStart, K, 32, tid);
            load_tensor(sb + BUF_B + (NSLOT - 1) * TEN_B, Bh, colStart, K, 32, tid);
            CP_COMMIT();
        }
    }

    int bufIdx = 0;
    for (int c = 0; c < NC; c++) {
        if (c + 1 < NC) { CP_WAIT(1); } else { CP_WAIT(0); }
        __syncthreads();

        if (c + 2 < NC) {
            int nIdx = bufIdx + 2; if (nIdx >= STAGES) nIdx -= STAGES;
            const uint32_t nbuf = sb + (uint32_t)nIdx * BUF_B;
            const int kofs = (c + 2) * 32;
            load_tensor(nbuf + 0 * TEN_B, Ah, rowStart, K, kofs, tid);
            if (NPROD == 2) load_tensor(nbuf + 1 * TEN_B, Al, rowStart, K, kofs, tid);
            load_tensor(nbuf + (NSLOT - 1) * TEN_B, Bh, colStart, K, kofs, tid);
            CP_COMMIT();
        }

        const uint32_t buf = sb + (uint32_t)bufIdx * BUF_B;
#pragma unroll
        for (int k0 = 0; k0 < 32; k0 += 16) {
            uint32_t ah[2][4], al[2][4], bh[4][4];
#pragma unroll
            for (int mt = 0; mt < 2; mt++) {
                uint32_t ao = (uint32_t)((a_row + mt * 16) * LDS_T + k0 + a_col) * 2;
                ldsm4(ah[mt], buf + 0 * TEN_B + ao);
                if (NPROD == 2) ldsm4(al[mt], buf + 1 * TEN_B + ao);
            }
#pragma unroll
            for (int np = 0; np < 4; np++) {
                uint32_t bo = (uint32_t)((b_row + np * 16) * LDS_T + k0 + b_col) * 2;
                ldsm4(bh[np], buf + (NSLOT - 1) * TEN_B + bo);
            }
            // pass 1: ah * bh
#pragma unroll
            for (int mt = 0; mt < 2; mt++)
#pragma unroll
                for (int np = 0; np < 4; np++) {
                    mma16816(acc[mt][2 * np + 0], ah[mt], &bh[np][0]);
                    mma16816(acc[mt][2 * np + 1], ah[mt], &bh[np][2]);
                }
            // pass 2: al * bh
            if (NPROD == 2) {
#pragma unroll
                for (int mt = 0; mt < 2; mt++)
#pragma unroll
                    for (int np = 0; np < 4; np++) {
                        mma16816(acc[mt][2 * np + 0], al[mt], &bh[np][0]);
                        mma16816(acc[mt][2 * np + 1], al[mt], &bh[np][2]);
                    }
            }
        }
        bufIdx++; if (bufIdx >= STAGES) bufIdx = 0;
    }

    // epilogue: registers -> gmem
#pragma unroll
    for (int mt = 0; mt < 2; mt++)
#pragma unroll
        for (int nt = 0; nt < 8; nt++) {
            const float* a = acc[mt][nt];
            int r0 = rowStart + warp_m * 32 + mt * 16 + (lane >> 2);
            int c0 = colStart + warp_n * 64 + nt * 8 + (lane & 3) * 2;
#pragma unroll
            for (int half = 0; half < 2; half++) {
                int gr = r0 + half * 8;
                float x0 = a[half * 2 + 0], x1 = a[half * 2 + 1];
                size_t o = cofs + (size_t)gr * N + c0;
                if (EPI == EPI_F32) {
                    *(float2*)(Cf + o) = make_float2(x0, x1);
                } else if (EPI == EPI_QOUT) {
                    *(float2*)(Cf + o) = make_float2(x0, x1);
                    __half h0, l0, h1, l1;
                    split1(x0, h0, l0); split1(x1, h1, l1);
                    *(__half2*)(Ch + o) = __halves2half2(h0, h1);
                    *(__half2*)(Cl + o) = __halves2half2(l0, l1);
                } else if (EPI == EPI_SCORES) {
                    // masked entries (col > row) may be garbage; never read.
                    *(float2*)(Cf + o) = make_float2(x0 * scale, x1 * scale);
                } else if (EPI == EPI_RESID) {
                    float2 e = *(const float2*)(Ef + o);
                    x0 += e.x; x1 += e.y;
                    __half h0, l0, h1, l1;
                    split1(x0, h0, l0); split1(x1, h1, l1);
                    *(__half2*)(Ch + o) = __halves2half2(h0, h1);
                    *(__half2*)(Cl + o) = __halves2half2(l0, l1);
                } else if (EPI == EPI_BIAS) {
                    x0 += Ef[c0]; x1 += Ef[c0 + 1];
                    *(float2*)(Cf + o) = make_float2(x0, x1);
                } else if (EPI == EPI_SWISH) {
                    x0 = x0 / (1.f + expf(-x0));
                    x1 = x1 / (1.f + expf(-x1));
                    __half h0, l0, h1, l1;
                    split1(x0, h0, l0); split1(x1, h1, l1);
                    *(__half2*)(Ch + o) = __halves2half2(h0, h1);
                    *(__half2*)(Cl + o) = __halves2half2(l0, l1);
                }
            }
        }
}

// ---------------------------------------------------------------------------
extern "C" void kernel_launch(void* const* d_in, const int* in_sizes, int n_in,
                              void* d_out, int out_size) {
    const float* x    = (const float*)d_in[0];
    const float* wi   = (const float*)d_in[2];
    const float* ok   = (const float*)d_in[3];
    const float* bias = (const float*)d_in[4];
    float* out = (float*)d_out;
    int H = in_sizes[3] / (DD * DD);

    float *q, *w2, *sc, *hn;
    __half *xh, *xl, *wt16, *w2t16, *qh, *ql, *qt16;
    __half *pph, *heh, *hel, *nh, *nl, *th, *tl;
    cudaGetSymbolAddress((void**)&q,     g_q);
    cudaGetSymbolAddress((void**)&w2,    g_w2);
    cudaGetSymbolAddress((void**)&sc,    g_sc);
    cudaGetSymbolAddress((void**)&hn,    g_hn);
    cudaGetSymbolAddress((void**)&xh,    g_xh);    cudaGetSymbolAddress((void**)&xl,   g_xl);
    cudaGetSymbolAddress((void**)&wt16,  g_wt16);
    cudaGetSymbolAddress((void**)&w2t16, g_w2t16);
    cudaGetSymbolAddress((void**)&qh,    g_qh);    cudaGetSymbolAddress((void**)&ql,   g_ql);
    cudaGetSymbolAddress((void**)&qt16,  g_qt16);
    cudaGetSymbolAddress((void**)&pph,   g_ph);
    cudaGetSymbolAddress((void**)&heh,   g_heh);   cudaGetSymbolAddress((void**)&hel,  g_hel);
    cudaGetSymbolAddress((void**)&nh,    g_nh);    cudaGetSymbolAddress((void**)&nl,   g_nl);
    cudaGetSymbolAddress((void**)&th,    g_th);    cudaGetSymbolAddress((void**)&tl,   g_tl);

    const int SM3 = STAGES * 3 * TEN_B;   // NPROD=2 kernels: 92160 B
    const int SM2 = STAGES * 2 * TEN_B;   // NPROD=1 kernels: 61440 B

    cudaFuncSetAttribute((const void*)gemm_tc<EPI_QOUT,   false, false, 2>, cudaFuncAttributeMaxDynamicSharedMemorySize, SM3);
    cudaFuncSetAttribute((const void*)gemm_tc<EPI_SCORES, true,  false, 2>, cudaFuncAttributeMaxDynamicSharedMemorySize, SM3);
    cudaFuncSetAttribute((const void*)gemm_tc<EPI_RESID,  false, true,  1>, cudaFuncAttributeMaxDynamicSharedMemorySize, SM2);
    cudaFuncSetAttribute((const void*)gemm_tc<EPI_BIAS,   false, false, 2>, cudaFuncAttributeMaxDynamicSharedMemorySize, SM3);
    cudaFuncSetAttribute((const void*)gemm_tc<EPI_SWISH,  false, false, 2>, cudaFuncAttributeMaxDynamicSharedMemorySize, SM3);
    cudaFuncSetAttribute((const void*)gemm_tc<EPI_F32,    false, false, 2>, cudaFuncAttributeMaxDynamicSharedMemorySize, SM3);

    // --- preprocessing ---
    split_kernel<<<(MT * DD / 4 + 255) / 256, 256>>>(x, xh, xl, MT * DD / 4);
    transpose_h_kernel<<<dim3(32, 32, 1), dim3(32, 8)>>>(wi, wt16, DD, DD, 0, 0);
    w2_reduce_kernel<<<(DD * DD + 255) / 256, 256>>>(ok, w2, H);
    transpose_h_kernel<<<dim3(32, 32, 1), dim3(32, 8)>>>(w2, w2t16, DD, DD, 0, 0);

    // q = x @ wi  (A split, B = wi^T fp16)  -> q fp32 + hi/lo
    gemm_tc<EPI_QOUT, false, false, 2><<<dim3(DD / 128, MT / 128, 1), 256, SM3>>>(
        MT, DD, DD, xh, xl, wt16, q, qh, ql, nullptr, 0.f, 0, 0, 0);

    // q^T per batch (single fp16, B operand for P@V)
    transpose_h_kernel<<<dim3(32, 64, BB), dim3(32, 8)>>>(
        q, qt16, SS, DD, (long)SS * DD, (long)SS * DD);

    // scores = (q @ q^T)/32  — A split, B = qh single (2 products), tri-skip
    gemm_tc<EPI_SCORES, true, false, 2><<<dim3(SS / 128, SS / 128, BB), 256, SM3>>>(
        SS, SS, DD, qh, ql, qh, sc, nullptr, nullptr, nullptr, 1.0f / 32.0f,
        (long)SS * DD, (long)SS * DD, (long)SS * SS);

    // causal softmax -> P fp16 (zeros to 128-padded boundary)
    softmax_kernel<<<BB * SS, 256>>>(sc, pph);

    // head = q + P @ q   (single product: P16 x q16^T, causal K clamp)
    gemm_tc<EPI_RESID, false, true, 1><<<dim3(DD / 128, SS / 128, BB), 256, SM2>>>(
        SS, DD, SS, pph, nullptr, qt16, nullptr, heh, hel, q, 0.f,
        (long)SS * SS, (long)SS * DD, (long)SS * DD);

    // h = head @ W2 + bias -> fp32
    gemm_tc<EPI_BIAS, false, false, 2><<<dim3(DD / 128, MT / 128, 1), 256, SM3>>>(
        MT, DD, DD, heh, hel, w2t16, hn, nullptr, nullptr, bias, 0.f, 0, 0, 0);

    // LayerNorm -> hi/lo
    layernorm_kernel<<<MT, 256>>>(hn, nh, nl);

    // t = swish(h @ wi) -> hi/lo
    gemm_tc<EPI_SWISH, false, false, 2><<<dim3(DD / 128, MT / 128, 1), 256, SM3>>>(
        MT, DD, DD, nh, nl, wt16, nullptr, th, tl, nullptr, 0.f, 0, 0, 0);

    // out = t @ wi -> fp32
    gemm_tc<EPI_F32, false, false, 2><<<dim3(DD / 128, MT / 128, 1), 256, SM3>>>(
        MT, DD, DD, th, tl, wt16, out, nullptr, nullptr, nullptr, 0.f, 0, 0, 0);
}

// round 8
// speedup vs baseline: 1.8176x; 1.7213x over previous
#include <cuda_runtime.h>
#include <cuda_fp16.h>
#include <math.h>
#include <stdint.h>

// ---------------------------------------------------------------------------
// Problem constants
// ---------------------------------------------------------------------------
#define DD 1024
#define SS 2048
#define BB 2
#define MT (BB * SS)          // 4096

// ---------------------------------------------------------------------------
// Scratch (device globals; no allocation allowed)
// ---------------------------------------------------------------------------
__device__ __half g_xh[MT * DD], g_xl[MT * DD];
__device__ __half g_wt16[DD * DD];                    // wi^T fp16
__device__ float  g_w2[DD * DD];
__device__ __half g_w2t16[DD * DD];                   // W2^T fp16
__device__ float  g_q[MT * DD];
__device__ __half g_qh[MT * DD], g_ql[MT * DD];
__device__ __half g_qt16[MT * DD];                    // q^T per batch, fp16
__device__ float  g_sc[(size_t)BB * SS * SS];
__device__ __half g_ph[(size_t)BB * SS * SS];         // softmax P (fp16)
__device__ __half g_heh[MT * DD], g_hel[MT * DD];     // head hi/lo
__device__ float  g_hn[MT * DD];                      // h (pre-LN)
__device__ __half g_nh[MT * DD];                      // LN(h) fp16
__device__ __half g_th[MT * DD];                      // swish out fp16

// ---------------------------------------------------------------------------
// PTX helpers (baseline ISA only)
// ---------------------------------------------------------------------------
__device__ __forceinline__ uint32_t smem_to_u32(const void* p) {
    uint32_t a;
    asm("{ .reg .u64 t; cvta.to.shared.u64 t, %1; cvt.u32.u64 %0, t; }"
        : "=r"(a) : "l"(p));
    return a;
}
__device__ __forceinline__ void cpasync16(uint32_t dst, const void* src) {
    asm volatile("cp.async.cg.shared.global [%0], [%1], 16;" :: "r"(dst), "l"(src));
}
#define CP_COMMIT() asm volatile("cp.async.commit_group;" ::: "memory")
#define CP_WAIT(n)  asm volatile("cp.async.wait_group %0;" :: "n"(n) : "memory")

__device__ __forceinline__ void ldsm4(uint32_t* r, uint32_t addr) {
    asm volatile("ldmatrix.sync.aligned.m8n8.x4.shared.b16 {%0,%1,%2,%3}, [%4];"
                 : "=r"(r[0]), "=r"(r[1]), "=r"(r[2]), "=r"(r[3]) : "r"(addr));
}
__device__ __forceinline__ void mma16816(float* c, const uint32_t* a, const uint32_t* b) {
    asm volatile(
        "mma.sync.aligned.m16n8k16.row.col.f32.f16.f16.f32 "
        "{%0,%1,%2,%3}, {%4,%5,%6,%7}, {%8,%9}, {%0,%1,%2,%3};"
        : "+f"(c[0]), "+f"(c[1]), "+f"(c[2]), "+f"(c[3])
        : "r"(a[0]), "r"(a[1]), "r"(a[2]), "r"(a[3]), "r"(b[0]), "r"(b[1]));
}

// ---------------------------------------------------------------------------
// fp32 -> fp16 hi/lo split
// ---------------------------------------------------------------------------
__device__ __forceinline__ void split1(float v, __half& h, __half& l) {
    h = __float2half(v);
    l = __float2half(v - __half2float(h));
}

// ---------------------------------------------------------------------------
// Elementwise / reshape kernels
// ---------------------------------------------------------------------------
__global__ void split_kernel(const float* __restrict__ in,
                             __half* __restrict__ oh,
                             __half* __restrict__ ol, int n4) {
    int i = blockIdx.x * blockDim.x + threadIdx.x;
    if (i >= n4) return;
    float4 v = ((const float4*)in)[i];
    __half h, l;
    size_t b = (size_t)i * 4;
    split1(v.x, h, l); oh[b + 0] = h; ol[b + 0] = l;
    split1(v.y, h, l); oh[b + 1] = h; ol[b + 1] = l;
    split1(v.z, h, l); oh[b + 2] = h; ol[b + 2] = l;
    split1(v.w, h, l); oh[b + 3] = h; ol[b + 3] = l;
}

// out[c][r] = fp16(in[r][c]); out dims [C,R]; z-batched
__global__ void transpose_h_kernel(const float* __restrict__ in,
                                   __half* __restrict__ o16,
                                   int R, int C, long sin, long sout) {
    __shared__ float t[32][33];
    in += (size_t)blockIdx.z * sin;
    o16 += (size_t)blockIdx.z * sout;
    int r0 = blockIdx.y * 32, c0 = blockIdx.x * 32;
    for (int i = threadIdx.y; i < 32; i += 8)
        t[i][threadIdx.x] = in[(size_t)(r0 + i) * C + c0 + threadIdx.x];
    __syncthreads();
    for (int i = threadIdx.y; i < 32; i += 8) {
        size_t o = (size_t)(c0 + i) * R + r0 + threadIdx.x;
        o16[o] = __float2half(t[threadIdx.x][i]);
    }
}

__global__ void w2_reduce_kernel(const float* __restrict__ ok,
                                 float* __restrict__ w2, int H) {
    int idx = blockIdx.x * blockDim.x + threadIdx.x;
    if (idx >= DD * DD) return;
    int i = idx / DD, j = idx % DD;
    float s = 0.f;
    for (int h = 0; h < H; h++) s += ok[(size_t)(h * DD + i) * DD + j];
    w2[idx] = s;
}

// Causal softmax. One block per (batch,row). Reads cols [0, L); writes P (fp16)
// for cols [0, Kc), Kc = ceil128(L); zeros beyond L. P@V clamps K to Kc.
__global__ void softmax_kernel(const float* __restrict__ S,
                               __half* __restrict__ ph) {
    __shared__ float red[256];
    const int tid = threadIdx.x;
    const int L = (blockIdx.x & (SS - 1)) + 1;
    const int Kc = (L + 127) & ~127;
    const size_t base = (size_t)blockIdx.x * SS;

    float vals[8];
    float m = -3.0e38f;
    int n = 0;
    for (int c = tid; c < L; c += 256) {
        float v = S[base + c];
        vals[n++] = v;
        m = fmaxf(m, v);
    }
    red[tid] = m; __syncthreads();
    for (int s = 128; s > 0; s >>= 1) { if (tid < s) red[tid] = fmaxf(red[tid], red[tid + s]); __syncthreads(); }
    m = red[0]; __syncthreads();

    float sum = 0.f;
#pragma unroll 8
    for (int i = 0; i < n; i++) { vals[i] = expf(vals[i] - m); sum += vals[i]; }
    red[tid] = sum; __syncthreads();
    for (int s = 128; s > 0; s >>= 1) { if (tid < s) red[tid] += red[tid + s]; __syncthreads(); }
    float inv = 1.0f / red[0];

    n = 0;
    for (int c = tid; c < Kc; c += 256) {
        float p = (c < L) ? vals[n] * inv : 0.f;
        if (c < L) n++;
        ph[base + c] = __float2half(p);
    }
}

// LayerNorm -> single fp16
__global__ void layernorm_kernel(const float* __restrict__ H,
                                 __half* __restrict__ oh) {
    __shared__ float red[256];
    int tid = threadIdx.x;
    size_t base = (size_t)blockIdx.x * DD;
    float4 v = ((const float4*)(H + base))[tid];

    red[tid] = v.x + v.y + v.z + v.w; __syncthreads();
    for (int s = 128; s > 0; s >>= 1) { if (tid < s) red[tid] += red[tid + s]; __syncthreads(); }
    float mean = red[0] * (1.0f / DD); __syncthreads();
    red[tid] = v.x * v.x + v.y * v.y + v.z * v.z + v.w * v.w; __syncthreads();
    for (int s = 128; s > 0; s >>= 1) { if (tid < s) red[tid] += red[tid + s]; __syncthreads(); }
    float msq = red[0] * (1.0f / DD);
    float inv = 1.0f / sqrtf(msq - mean * mean + 1e-5f);

    size_t o = base + (size_t)tid * 4;
    oh[o + 0] = __float2half((v.x - mean) * inv);
    oh[o + 1] = __float2half((v.y - mean) * inv);
    oh[o + 2] = __float2half((v.z - mean) * inv);
    oh[o + 3] = __float2half((v.w - mean) * inv);
}

// ---------------------------------------------------------------------------
// HMMA fp16 split GEMM: C[z] = A[z] @ B[z]^T  (A:[M,K], B:[N,K])
// NPROD=2: A hi/lo split, B single fp16 -> ah*b + al*b
// NPROD=1: A single fp16, B single fp16 -> ah*b
// 128x128 block tile, BK=32, 8 warps (4M x 2N), warp tile 32x64, 3-stage pipe.
// np-outer B loading keeps live registers < 128 so __launch_bounds__(256,2)
// gives 2 resident CTAs without inner-loop spills.
// ---------------------------------------------------------------------------
enum { EPI_F32 = 0, EPI_QOUT = 1, EPI_SCORES = 2, EPI_RESID = 3, EPI_BIAS = 4,
       EPI_SWISH16 = 5 };

#define LDS_T 40                        // smem row stride (halves): conflict-free ldmatrix
#define TEN_B (128 * LDS_T * 2)         // one tensor tile: 10240 B
#define STAGES 3

__device__ __forceinline__ void load_tensor(uint32_t sdst, const __half* g,
                                            int base_row, int ldK, int kofs, int tid) {
#pragma unroll
    for (int i = 0; i < 2; i++) {
        int v = tid * 2 + i;                 // 0..511
        int row = v >> 2, cseg = v & 3;
        uint32_t dst = sdst + (uint32_t)(row * LDS_T + cseg * 8) * 2;
        cpasync16(dst, g + (size_t)(base_row + row) * ldK + kofs + cseg * 8);
    }
}

template <int EPI, bool CAUSAL, bool KCLAMP, int NPROD>
__global__ __launch_bounds__(256, 2) void gemm_tc(
    int M, int N, int K,
    const __half* __restrict__ Ah, const __half* __restrict__ Al,
    const __half* __restrict__ Bh,
    float* __restrict__ Cf,
    __half* __restrict__ Ch, __half* __restrict__ Cl,
    const float* __restrict__ Ef, float scale,
    long sA, long sB, long sC) {
    extern __shared__ char smem[];
    constexpr int NSLOT = NPROD + 1;
    constexpr uint32_t BUF_B = NSLOT * TEN_B;
    const int tid = threadIdx.x;
    const int rowStart = blockIdx.y * 128, colStart = blockIdx.x * 128;
    const int z = blockIdx.z;

    // Fully masked score tile: nothing to do (softmax never reads it).
    if (CAUSAL && colStart > rowStart) return;

    Ah += (size_t)z * sA;
    if (NPROD == 2) Al += (size_t)z * sA;
    Bh += (size_t)z * sB;
    const size_t cofs = (size_t)z * sC;

    const uint32_t sb = smem_to_u32(smem);
    const int lane = tid & 31, wid = tid >> 5;
    const int warp_m = wid & 3, warp_n = wid >> 2;

    const int NC = (KCLAMP ? (rowStart + 128) : K) / 32;

    const int a_row = warp_m * 32 + (lane & 15);
    const int a_col = (lane >> 4) * 8;
    const int b_row = warp_n * 64 + (lane & 7) + ((lane >> 4) & 1) * 8;
    const int b_col = ((lane >> 3) & 1) * 8;

    float acc[2][8][4];
#pragma unroll
    for (int i = 0; i < 2; i++)
#pragma unroll
        for (int j = 0; j < 8; j++)
#pragma unroll
            for (int q = 0; q < 4; q++) acc[i][j][q] = 0.f;

    // prologue: stages 0, 1
    {
        load_tensor(sb + 0 * TEN_B, Ah, rowStart, K, 0, tid);
        if (NPROD == 2) load_tensor(sb + 1 * TEN_B, Al, rowStart, K, 0, tid);
        load_tensor(sb + (NSLOT - 1) * TEN_B, Bh, colStart, K, 0, tid);
        CP_COMMIT();
        if (NC > 1) {
            load_tensor(sb + BUF_B + 0 * TEN_B, Ah, rowStart, K, 32, tid);
            if (NPROD == 2) load_tensor(sb + BUF_B + 1 * TEN_B, Al, rowStart, K, 32, tid);
            load_tensor(sb + BUF_B + (NSLOT - 1) * TEN_B, Bh, colStart, K, 32, tid);
            CP_COMMIT();
        }
    }

    int bufIdx = 0;
    for (int c = 0; c < NC; c++) {
        if (c + 1 < NC) { CP_WAIT(1); } else { CP_WAIT(0); }
        __syncthreads();

        if (c + 2 < NC) {
            int nIdx = bufIdx + 2; if (nIdx >= STAGES) nIdx -= STAGES;
            const uint32_t nbuf = sb + (uint32_t)nIdx * BUF_B;
            const int kofs = (c + 2) * 32;
            load_tensor(nbuf + 0 * TEN_B, Ah, rowStart, K, kofs, tid);
            if (NPROD == 2) load_tensor(nbuf + 1 * TEN_B, Al, rowStart, K, kofs, tid);
            load_tensor(nbuf + (NSLOT - 1) * TEN_B, Bh, colStart, K, kofs, tid);
            CP_COMMIT();
        }

        const uint32_t buf = sb + (uint32_t)bufIdx * BUF_B;
#pragma unroll
        for (int k0 = 0; k0 < 32; k0 += 16) {
            uint32_t ah[2][4], al[2][4];
#pragma unroll
            for (int mt = 0; mt < 2; mt++) {
                uint32_t ao = (uint32_t)((a_row + mt * 16) * LDS_T + k0 + a_col) * 2;
                ldsm4(ah[mt], buf + 0 * TEN_B + ao);
                if (NPROD == 2) ldsm4(al[mt], buf + 1 * TEN_B + ao);
            }
            // np-outer: one B fragment live at a time (register pressure)
#pragma unroll
            for (int np = 0; np < 4; np++) {
                uint32_t bh[4];
                uint32_t bo = (uint32_t)((b_row + np * 16) * LDS_T + k0 + b_col) * 2;
                ldsm4(bh, buf + (NSLOT - 1) * TEN_B + bo);
                mma16816(acc[0][2 * np + 0], ah[0], &bh[0]);
                mma16816(acc[0][2 * np + 1], ah[0], &bh[2]);
                mma16816(acc[1][2 * np + 0], ah[1], &bh[0]);
                mma16816(acc[1][2 * np + 1], ah[1], &bh[2]);
                if (NPROD == 2) {
                    mma16816(acc[0][2 * np + 0], al[0], &bh[0]);
                    mma16816(acc[0][2 * np + 1], al[0], &bh[2]);
                    mma16816(acc[1][2 * np + 0], al[1], &bh[0]);
                    mma16816(acc[1][2 * np + 1], al[1], &bh[2]);
                }
            }
        }
        bufIdx++; if (bufIdx >= STAGES) bufIdx = 0;
    }

    // epilogue: registers -> gmem
#pragma unroll
    for (int mt = 0; mt < 2; mt++)
#pragma unroll
        for (int nt = 0; nt < 8; nt++) {
            const float* a = acc[mt][nt];
            int r0 = rowStart + warp_m * 32 + mt * 16 + (lane >> 2);
            int c0 = colStart + warp_n * 64 + nt * 8 + (lane & 3) * 2;
#pragma unroll
            for (int half = 0; half < 2; half++) {
                int gr = r0 + half * 8;
                float x0 = a[half * 2 + 0], x1 = a[half * 2 + 1];
                size_t o = cofs + (size_t)gr * N + c0;
                if (EPI == EPI_F32) {
                    *(float2*)(Cf + o) = make_float2(x0, x1);
                } else if (EPI == EPI_QOUT) {
                    *(float2*)(Cf + o) = make_float2(x0, x1);
                    __half h0, l0, h1, l1;
                    split1(x0, h0, l0); split1(x1, h1, l1);
                    *(__half2*)(Ch + o) = __halves2half2(h0, h1);
                    *(__half2*)(Cl + o) = __halves2half2(l0, l1);
                } else if (EPI == EPI_SCORES) {
                    // masked entries (col > row) may be garbage; never read.
                    *(float2*)(Cf + o) = make_float2(x0 * scale, x1 * scale);
                } else if (EPI == EPI_RESID) {
                    float2 e = *(const float2*)(Ef + o);
                    x0 += e.x; x1 += e.y;
                    __half h0, l0, h1, l1;
                    split1(x0, h0, l0); split1(x1, h1, l1);
                    *(__half2*)(Ch + o) = __halves2half2(h0, h1);
                    *(__half2*)(Cl + o) = __halves2half2(l0, l1);
                } else if (EPI == EPI_BIAS) {
                    x0 += Ef[c0]; x1 += Ef[c0 + 1];
                    *(float2*)(Cf + o) = make_float2(x0, x1);
                } else if (EPI == EPI_SWISH16) {
                    x0 = x0 / (1.f + expf(-x0));
                    x1 = x1 / (1.f + expf(-x1));
                    *(__half2*)(Ch + o) =
                        __halves2half2(__float2half(x0), __float2half(x1));
                }
            }
        }
}

// ---------------------------------------------------------------------------
extern "C" void kernel_launch(void* const* d_in, const int* in_sizes, int n_in,
                              void* d_out, int out_size) {
    const float* x    = (const float*)d_in[0];
    const float* wi   = (const float*)d_in[2];
    const float* ok   = (const float*)d_in[3];
    const float* bias = (const float*)d_in[4];
    float* out = (float*)d_out;
    int H = in_sizes[3] / (DD * DD);

    float *q, *w2, *sc, *hn;
    __half *xh, *xl, *wt16, *w2t16, *qh, *ql, *qt16;
    __half *pph, *heh, *hel, *nh, *th;
    cudaGetSymbolAddress((void**)&q,     g_q);
    cudaGetSymbolAddress((void**)&w2,    g_w2);
    cudaGetSymbolAddress((void**)&sc,    g_sc);
    cudaGetSymbolAddress((void**)&hn,    g_hn);
    cudaGetSymbolAddress((void**)&xh,    g_xh);    cudaGetSymbolAddress((void**)&xl,   g_xl);
    cudaGetSymbolAddress((void**)&wt16,  g_wt16);
    cudaGetSymbolAddress((void**)&w2t16, g_w2t16);
    cudaGetSymbolAddress((void**)&qh,    g_qh);    cudaGetSymbolAddress((void**)&ql,   g_ql);
    cudaGetSymbolAddress((void**)&qt16,  g_qt16);
    cudaGetSymbolAddress((void**)&pph,   g_ph);
    cudaGetSymbolAddress((void**)&heh,   g_heh);   cudaGetSymbolAddress((void**)&hel,  g_hel);
    cudaGetSymbolAddress((void**)&nh,    g_nh);
    cudaGetSymbolAddress((void**)&th,    g_th);

    const int SM3 = STAGES * 3 * TEN_B;   // NPROD=2 kernels: 92160 B
    const int SM2 = STAGES * 2 * TEN_B;   // NPROD=1 kernels: 61440 B

    cudaFuncSetAttribute((const void*)gemm_tc<EPI_QOUT,    false, false, 2>, cudaFuncAttributeMaxDynamicSharedMemorySize, SM3);
    cudaFuncSetAttribute((const void*)gemm_tc<EPI_SCORES,  true,  false, 2>, cudaFuncAttributeMaxDynamicSharedMemorySize, SM3);
    cudaFuncSetAttribute((const void*)gemm_tc<EPI_RESID,   false, true,  1>, cudaFuncAttributeMaxDynamicSharedMemorySize, SM2);
    cudaFuncSetAttribute((const void*)gemm_tc<EPI_BIAS,    false, false, 2>, cudaFuncAttributeMaxDynamicSharedMemorySize, SM3);
    cudaFuncSetAttribute((const void*)gemm_tc<EPI_SWISH16, false, false, 1>, cudaFuncAttributeMaxDynamicSharedMemorySize, SM2);
    cudaFuncSetAttribute((const void*)gemm_tc<EPI_F32,     false, false, 1>, cudaFuncAttributeMaxDynamicSharedMemorySize, SM2);

    // --- preprocessing ---
    split_kernel<<<(MT * DD / 4 + 255) / 256, 256>>>(x, xh, xl, MT * DD / 4);
    transpose_h_kernel<<<dim3(32, 32, 1), dim3(32, 8)>>>(wi, wt16, DD, DD, 0, 0);
    w2_reduce_kernel<<<(DD * DD + 255) / 256, 256>>>(ok, w2, H);
    transpose_h_kernel<<<dim3(32, 32, 1), dim3(32, 8)>>>(w2, w2t16, DD, DD, 0, 0);

    // q = x @ wi  (A split, B = wi^T fp16)  -> q fp32 + hi/lo
    gemm_tc<EPI_QOUT, false, false, 2><<<dim3(DD / 128, MT / 128, 1), 256, SM3>>>(
        MT, DD, DD, xh, xl, wt16, q, qh, ql, nullptr, 0.f, 0, 0, 0);

    // q^T per batch (single fp16, B operand for P@V)
    transpose_h_kernel<<<dim3(32, 64, BB), dim3(32, 8)>>>(
        q, qt16, SS, DD, (long)SS * DD, (long)SS * DD);

    // scores = (q @ q^T)/32  — A split, B = qh single (2 products), tri-skip
    gemm_tc<EPI_SCORES, true, false, 2><<<dim3(SS / 128, SS / 128, BB), 256, SM3>>>(
        SS, SS, DD, qh, ql, qh, sc, nullptr, nullptr, nullptr, 1.0f / 32.0f,
        (long)SS * DD, (long)SS * DD, (long)SS * SS);

    // causal softmax -> P fp16 (zeros to 128-padded boundary)
    softmax_kernel<<<BB * SS, 256>>>(sc, pph);

    // head = q + P @ q   (single product, causal K clamp) -> head hi/lo
    gemm_tc<EPI_RESID, false, true, 1><<<dim3(DD / 128, SS / 128, BB), 256, SM2>>>(
        SS, DD, SS, pph, nullptr, qt16, nullptr, heh, hel, q, 0.f,
        (long)SS * SS, (long)SS * DD, (long)SS * DD);

    // h = head @ W2 + bias -> fp32
    gemm_tc<EPI_BIAS, false, false, 2><<<dim3(DD / 128, MT / 128, 1), 256, SM3>>>(
        MT, DD, DD, heh, hel, w2t16, hn, nullptr, nullptr, bias, 0.f, 0, 0, 0);

    // LayerNorm -> single fp16
    layernorm_kernel<<<MT, 256>>>(hn, nh);

    // t = swish(LN(h) @ wi)  (single product) -> fp16
    gemm_tc<EPI_SWISH16, false, false, 1><<<dim3(DD / 128, MT / 128, 1), 256, SM2>>>(
        MT, DD, DD, nh, nullptr, wt16, nullptr, th, nullptr, nullptr, 0.f, 0, 0, 0);

    // out = t @ wi  (single product) -> fp32
    gemm_tc<EPI_F32, false, false, 1><<<dim3(DD / 128, MT / 128, 1), 256, SM2>>>(
        MT, DD, DD, th, nullptr, wt16, out, nullptr, nullptr, nullptr, 0.f, 0, 0, 0);
}

// round 9
// speedup vs baseline: 2.2690x; 1.2483x over previous
#include <cuda_runtime.h>
#include <cuda_fp16.h>
#include <math.h>
#include <stdint.h>

// ---------------------------------------------------------------------------
// Problem constants
// ---------------------------------------------------------------------------
#define DD 1024
#define SS 2048
#define BB 2
#define MT (BB * SS)          // 4096

// ---------------------------------------------------------------------------
// Scratch (device globals; no allocation allowed)
// ---------------------------------------------------------------------------
__device__ __half g_x16[MT * DD];                     // x fp16
__device__ __half g_wt16[DD * DD];                    // wi^T fp16
__device__ __half g_w2t16[DD * DD];                   // W2^T fp16 (fused reduce+T)
__device__ float  g_q[MT * DD];                       // q fp32 (residual source)
__device__ __half g_q16[MT * DD];                     // q fp16
__device__ __half g_qt16[MT * DD];                    // q^T per batch, fp16
__device__ float  g_sc[(size_t)BB * SS * SS];
__device__ __half g_p16[(size_t)BB * SS * SS];        // softmax P fp16
__device__ __half g_he16[MT * DD];                    // head fp16
__device__ float  g_hn[MT * DD];                      // h (pre-LN) fp32
__device__ __half g_nh[MT * DD];                      // LN(h) fp16
__device__ __half g_t16[MT * DD];                     // swish out fp16

// ---------------------------------------------------------------------------
// PTX helpers (baseline ISA only)
// ---------------------------------------------------------------------------
__device__ __forceinline__ uint32_t smem_to_u32(const void* p) {
    uint32_t a;
    asm("{ .reg .u64 t; cvta.to.shared.u64 t, %1; cvt.u32.u64 %0, t; }"
        : "=r"(a) : "l"(p));
    return a;
}
__device__ __forceinline__ void cpasync16(uint32_t dst, const void* src) {
    asm volatile("cp.async.cg.shared.global [%0], [%1], 16;" :: "r"(dst), "l"(src));
}
#define CP_COMMIT() asm volatile("cp.async.commit_group;" ::: "memory")
#define CP_WAIT(n)  asm volatile("cp.async.wait_group %0;" :: "n"(n) : "memory")

__device__ __forceinline__ void ldsm4(uint32_t* r, uint32_t addr) {
    asm volatile("ldmatrix.sync.aligned.m8n8.x4.shared.b16 {%0,%1,%2,%3}, [%4];"
                 : "=r"(r[0]), "=r"(r[1]), "=r"(r[2]), "=r"(r[3]) : "r"(addr));
}
__device__ __forceinline__ void mma16816(float* c, const uint32_t* a, const uint32_t* b) {
    asm volatile(
        "mma.sync.aligned.m16n8k16.row.col.f32.f16.f16.f32 "
        "{%0,%1,%2,%3}, {%4,%5,%6,%7}, {%8,%9}, {%0,%1,%2,%3};"
        : "+f"(c[0]), "+f"(c[1]), "+f"(c[2]), "+f"(c[3])
        : "r"(a[0]), "r"(a[1]), "r"(a[2]), "r"(a[3]), "r"(b[0]), "r"(b[1]));
}

// ---------------------------------------------------------------------------
// Elementwise / reshape kernels
// ---------------------------------------------------------------------------
__global__ void tofp16_kernel(const float* __restrict__ in,
                              __half* __restrict__ o, int n4) {
    int i = blockIdx.x * blockDim.x + threadIdx.x;
    if (i >= n4) return;
    float4 v = ((const float4*)in)[i];
    __half2 a = __halves2half2(__float2half(v.x), __float2half(v.y));
    __half2 b = __halves2half2(__float2half(v.z), __float2half(v.w));
    ((__half2*)o)[i * 2 + 0] = a;
    ((__half2*)o)[i * 2 + 1] = b;
}

// out[c][r] = fp16(in[r][c]); in fp32 [R?]; generic square transpose, z-batched
__global__ void transpose_h_kernel(const float* __restrict__ in,
                                   __half* __restrict__ o16,
                                   int R, int C, long sin, long sout) {
    __shared__ float t[32][33];
    in += (size_t)blockIdx.z * sin;
    o16 += (size_t)blockIdx.z * sout;
    int r0 = blockIdx.y * 32, c0 = blockIdx.x * 32;
    for (int i = threadIdx.y; i < 32; i += 8)
        t[i][threadIdx.x] = in[(size_t)(r0 + i) * C + c0 + threadIdx.x];
    __syncthreads();
    for (int i = threadIdx.y; i < 32; i += 8) {
        size_t o = (size_t)(c0 + i) * R + r0 + threadIdx.x;
        o16[o] = __float2half(t[threadIdx.x][i]);
    }
}

// fp16 -> fp16 transpose (for q^T), z-batched
__global__ void transpose16_kernel(const __half* __restrict__ in,
                                   __half* __restrict__ o16,
                                   int R, int C, long s) {
    __shared__ __half t[32][33];
    in += (size_t)blockIdx.z * s;
    o16 += (size_t)blockIdx.z * s;
    int r0 = blockIdx.y * 32, c0 = blockIdx.x * 32;
    for (int i = threadIdx.y; i < 32; i += 8)
        t[i][threadIdx.x] = in[(size_t)(r0 + i) * C + c0 + threadIdx.x];
    __syncthreads();
    for (int i = threadIdx.y; i < 32; i += 8) {
        size_t o = (size_t)(c0 + i) * R + r0 + threadIdx.x;
        o16[o] = t[threadIdx.x][i];
    }
}

// Fused: W2^T[j][i] = fp16( sum_h ok[h*D + i][j] )
__global__ void w2t_kernel(const float* __restrict__ ok,
                           __half* __restrict__ w2t, int H) {
    __shared__ float t[32][33];
    int r0 = blockIdx.y * 32, c0 = blockIdx.x * 32;   // r=i (row of W2), c=j
    for (int i = threadIdx.y; i < 32; i += 8) {
        float s = 0.f;
        for (int h = 0; h < H; h++)
            s += ok[(size_t)(h * DD + r0 + i) * DD + c0 + threadIdx.x];
        t[i][threadIdx.x] = s;
    }
    __syncthreads();
    for (int i = threadIdx.y; i < 32; i += 8) {
        // output at [j][i]: j = c0 + i, i = r0 + threadIdx.x
        size_t o = (size_t)(c0 + i) * DD + r0 + threadIdx.x;
        w2t[o] = __float2half(t[threadIdx.x][i]);
    }
}

// Causal softmax. One block per (batch,row). Reads cols [0, L); writes P (fp16)
// for cols [0, Kc), Kc = ceil128(L); zeros beyond L. P@V clamps K to Kc.
__global__ void softmax_kernel(const float* __restrict__ S,
                               __half* __restrict__ ph) {
    __shared__ float red[256];
    const int tid = threadIdx.x;
    const int L = (blockIdx.x & (SS - 1)) + 1;
    const int Kc = (L + 127) & ~127;
    const size_t base = (size_t)blockIdx.x * SS;

    float vals[8];
    float m = -3.0e38f;
    int n = 0;
    for (int c = tid; c < L; c += 256) {
        float v = S[base + c];
        vals[n++] = v;
        m = fmaxf(m, v);
    }
    red[tid] = m; __syncthreads();
    for (int s = 128; s > 0; s >>= 1) { if (tid < s) red[tid] = fmaxf(red[tid], red[tid + s]); __syncthreads(); }
    m = red[0]; __syncthreads();

    float sum = 0.f;
#pragma unroll 8
    for (int i = 0; i < n; i++) { vals[i] = expf(vals[i] - m); sum += vals[i]; }
    red[tid] = sum; __syncthreads();
    for (int s = 128; s > 0; s >>= 1) { if (tid < s) red[tid] += red[tid + s]; __syncthreads(); }
    float inv = 1.0f / red[0];

    n = 0;
    for (int c = tid; c < Kc; c += 256) {
        float p = (c < L) ? vals[n] * inv : 0.f;
        if (c < L) n++;
        ph[base + c] = __float2half(p);
    }
}

// LayerNorm -> single fp16
__global__ void layernorm_kernel(const float* __restrict__ H,
                                 __half* __restrict__ oh) {
    __shared__ float red[256];
    int tid = threadIdx.x;
    size_t base = (size_t)blockIdx.x * DD;
    float4 v = ((const float4*)(H + base))[tid];

    red[tid] = v.x + v.y + v.z + v.w; __syncthreads();
    for (int s = 128; s > 0; s >>= 1) { if (tid < s) red[tid] += red[tid + s]; __syncthreads(); }
    float mean = red[0] * (1.0f / DD); __syncthreads();
    red[tid] = v.x * v.x + v.y * v.y + v.z * v.z + v.w * v.w; __syncthreads();
    for (int s = 128; s > 0; s >>= 1) { if (tid < s) red[tid] += red[tid + s]; __syncthreads(); }
    float msq = red[0] * (1.0f / DD);
    float inv = 1.0f / sqrtf(msq - mean * mean + 1e-5f);

    size_t o = base + (size_t)tid * 4;
    oh[o + 0] = __float2half((v.x - mean) * inv);
    oh[o + 1] = __float2half((v.y - mean) * inv);
    oh[o + 2] = __float2half((v.z - mean) * inv);
    oh[o + 3] = __float2half((v.w - mean) * inv);
}

// ---------------------------------------------------------------------------
// HMMA fp16 GEMM: C[z] = A[z] @ B[z]^T  (A:[M,K] fp16, B:[N,K] fp16, fp32 acc)
// 128x128 block tile, BK=32, 8 warps (4M x 2N), warp tile 32x64, 3-stage pipe.
// Single product per operand pair; attention softmax is a near-delta so fp16
// operand rounding contributes ~1e-4-level relative error only.
// __launch_bounds__(256, 2) + np-outer B loading: 2 CTAs/SM, no spills.
// ---------------------------------------------------------------------------
enum { EPI_F32 = 0, EPI_QOUT = 1, EPI_SCORES = 2, EPI_RESID16 = 3, EPI_BIAS = 4,
       EPI_SWISH16 = 5 };

#define LDS_T 40                        // smem row stride (halves): conflict-free ldmatrix
#define TEN_B (128 * LDS_T * 2)         // one tensor tile: 10240 B
#define STAGES 3
#define BUF_B (2 * TEN_B)               // A tile + B tile per stage
#define SMEM_BYTES (STAGES * BUF_B)     // 61440 B -> 2 CTAs/SM

__device__ __forceinline__ void load_tensor(uint32_t sdst, const __half* g,
                                            int base_row, int ldK, int kofs, int tid) {
#pragma unroll
    for (int i = 0; i < 2; i++) {
        int v = tid * 2 + i;                 // 0..511
        int row = v >> 2, cseg = v & 3;
        uint32_t dst = sdst + (uint32_t)(row * LDS_T + cseg * 8) * 2;
        cpasync16(dst, g + (size_t)(base_row + row) * ldK + kofs + cseg * 8);
    }
}

template <int EPI, bool CAUSAL, bool KCLAMP>
__global__ __launch_bounds__(256, 2) void gemm_tc(
    int M, int N, int K,
    const __half* __restrict__ A, const __half* __restrict__ B,
    float* __restrict__ Cf, __half* __restrict__ Ch,
    const float* __restrict__ Ef, float scale,
    long sA, long sB, long sC) {
    extern __shared__ char smem[];
    const int tid = threadIdx.x;
    const int rowStart = blockIdx.y * 128, colStart = blockIdx.x * 128;
    const int z = blockIdx.z;

    // Fully masked score tile: nothing to do (softmax never reads it).
    if (CAUSAL && colStart > rowStart) return;

    A += (size_t)z * sA;
    B += (size_t)z * sB;
    const size_t cofs = (size_t)z * sC;

    const uint32_t sb = smem_to_u32(smem);
    const int lane = tid & 31, wid = tid >> 5;
    const int warp_m = wid & 3, warp_n = wid >> 2;

    const int NC = (KCLAMP ? (rowStart + 128) : K) / 32;

    const int a_row = warp_m * 32 + (lane & 15);
    const int a_col = (lane >> 4) * 8;
    const int b_row = warp_n * 64 + (lane & 7) + ((lane >> 4) & 1) * 8;
    const int b_col = ((lane >> 3) & 1) * 8;

    float acc[2][8][4];
#pragma unroll
    for (int i = 0; i < 2; i++)
#pragma unroll
        for (int j = 0; j < 8; j++)
#pragma unroll
            for (int q = 0; q < 4; q++) acc[i][j][q] = 0.f;

    // prologue: stages 0, 1
    {
        load_tensor(sb + 0 * TEN_B, A, rowStart, K, 0, tid);
        load_tensor(sb + 1 * TEN_B, B, colStart, K, 0, tid);
        CP_COMMIT();
        if (NC > 1) {
            load_tensor(sb + BUF_B + 0 * TEN_B, A, rowStart, K, 32, tid);
            load_tensor(sb + BUF_B + 1 * TEN_B, B, colStart, K, 32, tid);
            CP_COMMIT();
        }
    }

    int bufIdx = 0;
    for (int c = 0; c < NC; c++) {
        if (c + 1 < NC) { CP_WAIT(1); } else { CP_WAIT(0); }
        __syncthreads();

        if (c + 2 < NC) {
            int nIdx = bufIdx + 2; if (nIdx >= STAGES) nIdx -= STAGES;
            const uint32_t nbuf = sb + (uint32_t)nIdx * BUF_B;
            const int kofs = (c + 2) * 32;
            load_tensor(nbuf + 0 * TEN_B, A, rowStart, K, kofs, tid);
            load_tensor(nbuf + 1 * TEN_B, B, colStart, K, kofs, tid);
            CP_COMMIT();
        }

        const uint32_t buf = sb + (uint32_t)bufIdx * BUF_B;
#pragma unroll
        for (int k0 = 0; k0 < 32; k0 += 16) {
            uint32_t ah[2][4];
#pragma unroll
            for (int mt = 0; mt < 2; mt++) {
                uint32_t ao = (uint32_t)((a_row + mt * 16) * LDS_T + k0 + a_col) * 2;
                ldsm4(ah[mt], buf + 0 * TEN_B + ao);
            }
            // np-outer: one B fragment live at a time (register pressure)
#pragma unroll
            for (int np = 0; np < 4; np++) {
                uint32_t bh[4];
                uint32_t bo = (uint32_t)((b_row + np * 16) * LDS_T + k0 + b_col) * 2;
                ldsm4(bh, buf + 1 * TEN_B + bo);
                mma16816(acc[0][2 * np + 0], ah[0], &bh[0]);
                mma16816(acc[0][2 * np + 1], ah[0], &bh[2]);
                mma16816(acc[1][2 * np + 0], ah[1], &bh[0]);
                mma16816(acc[1][2 * np + 1], ah[1], &bh[2]);
            }
        }
        bufIdx++; if (bufIdx >= STAGES) bufIdx = 0;
    }

    // epilogue: registers -> gmem
#pragma unroll
    for (int mt = 0; mt < 2; mt++)
#pragma unroll
        for (int nt = 0; nt < 8; nt++) {
            const float* a = acc[mt][nt];
            int r0 = rowStart + warp_m * 32 + mt * 16 + (lane >> 2);
            int c0 = colStart + warp_n * 64 + nt * 8 + (lane & 3) * 2;
#pragma unroll
            for (int half = 0; half < 2; half++) {
                int gr = r0 + half * 8;
                float x0 = a[half * 2 + 0], x1 = a[half * 2 + 1];
                size_t o = cofs + (size_t)gr * N + c0;
                if (EPI == EPI_F32) {
                    *(float2*)(Cf + o) = make_float2(x0, x1);
                } else if (EPI == EPI_QOUT) {
                    *(float2*)(Cf + o) = make_float2(x0, x1);
                    *(__half2*)(Ch + o) =
                        __halves2half2(__float2half(x0), __float2half(x1));
                } else if (EPI == EPI_SCORES) {
                    // masked entries (col > row) may be garbage; never read.
                    *(float2*)(Cf + o) = make_float2(x0 * scale, x1 * scale);
                } else if (EPI == EPI_RESID16) {
                    float2 e = *(const float2*)(Ef + o);
                    x0 += e.x; x1 += e.y;
                    *(__half2*)(Ch + o) =
                        __halves2half2(__float2half(x0), __float2half(x1));
                } else if (EPI == EPI_BIAS) {
                    x0 += Ef[c0]; x1 += Ef[c0 + 1];
                    *(float2*)(Cf + o) = make_float2(x0, x1);
                } else if (EPI == EPI_SWISH16) {
                    x0 = x0 / (1.f + expf(-x0));
                    x1 = x1 / (1.f + expf(-x1));
                    *(__half2*)(Ch + o) =
                        __halves2half2(__float2half(x0), __float2half(x1));
                }
            }
        }
}

// ---------------------------------------------------------------------------
extern "C" void kernel_launch(void* const* d_in, const int* in_sizes, int n_in,
                              void* d_out, int out_size) {
    const float* x    = (const float*)d_in[0];
    const float* wi   = (const float*)d_in[2];
    const float* ok   = (const float*)d_in[3];
    const float* bias = (const float*)d_in[4];
    float* out = (float*)d_out;
    int H = in_sizes[3] / (DD * DD);

    float *q, *sc, *hn;
    __half *x16, *wt16, *w2t16, *q16, *qt16, *p16, *he16, *nh, *t16;
    cudaGetSymbolAddress((void**)&q,     g_q);
    cudaGetSymbolAddress((void**)&sc,    g_sc);
    cudaGetSymbolAddress((void**)&hn,    g_hn);
    cudaGetSymbolAddress((void**)&x16,   g_x16);
    cudaGetSymbolAddress((void**)&wt16,  g_wt16);
    cudaGetSymbolAddress((void**)&w2t16, g_w2t16);
    cudaGetSymbolAddress((void**)&q16,   g_q16);
    cudaGetSymbolAddress((void**)&qt16,  g_qt16);
    cudaGetSymbolAddress((void**)&p16,   g_p16);
    cudaGetSymbolAddress((void**)&he16,  g_he16);
    cudaGetSymbolAddress((void**)&nh,    g_nh);
    cudaGetSymbolAddress((void**)&t16,   g_t16);

    cudaFuncSetAttribute((const void*)gemm_tc<EPI_QOUT,    false, false>, cudaFuncAttributeMaxDynamicSharedMemorySize, SMEM_BYTES);
    cudaFuncSetAttribute((const void*)gemm_tc<EPI_SCORES,  true,  false>, cudaFuncAttributeMaxDynamicSharedMemorySize, SMEM_BYTES);
    cudaFuncSetAttribute((const void*)gemm_tc<EPI_RESID16, false, true >, cudaFuncAttributeMaxDynamicSharedMemorySize, SMEM_BYTES);
    cudaFuncSetAttribute((const void*)gemm_tc<EPI_BIAS,    false, false>, cudaFuncAttributeMaxDynamicSharedMemorySize, SMEM_BYTES);
    cudaFuncSetAttribute((const void*)gemm_tc<EPI_SWISH16, false, false>, cudaFuncAttributeMaxDynamicSharedMemorySize, SMEM_BYTES);
    cudaFuncSetAttribute((const void*)gemm_tc<EPI_F32,     false, false>, cudaFuncAttributeMaxDynamicSharedMemorySize, SMEM_BYTES);

    // --- preprocessing ---
    tofp16_kernel<<<(MT * DD / 4 + 255) / 256, 256>>>(x, x16, MT * DD / 4);
    transpose_h_kernel<<<dim3(32, 32, 1), dim3(32, 8)>>>(wi, wt16, DD, DD, 0, 0);
    w2t_kernel<<<dim3(32, 32, 1), dim3(32, 8)>>>(ok, w2t16, H);

    // q = x @ wi  -> q fp32 + fp16
    gemm_tc<EPI_QOUT, false, false><<<dim3(DD / 128, MT / 128, 1), 256, SMEM_BYTES>>>(
        MT, DD, DD, x16, wt16, q, q16, nullptr, 0.f, 0, 0, 0);

    // q^T per batch (B operand for P@V)
    transpose16_kernel<<<dim3(32, 64, BB), dim3(32, 8)>>>(
        q16, qt16, SS, DD, (long)SS * DD);

    // scores = (q @ q^T)/32, lower-triangle tiles only
    gemm_tc<EPI_SCORES, true, false><<<dim3(SS / 128, SS / 128, BB), 256, SMEM_BYTES>>>(
        SS, SS, DD, q16, q16, sc, nullptr, nullptr, 1.0f / 32.0f,
        (long)SS * DD, (long)SS * DD, (long)SS * SS);

    // causal softmax -> P fp16 (zeros to 128-padded boundary)
    softmax_kernel<<<BB * SS, 256>>>(sc, p16);

    // head = q + P @ q   (causal K clamp) -> fp16
    gemm_tc<EPI_RESID16, false, true><<<dim3(DD / 128, SS / 128, BB), 256, SMEM_BYTES>>>(
        SS, DD, SS, p16, qt16, nullptr, he16, q, 0.f,
        (long)SS * SS, (long)SS * DD, (long)SS * DD);

    // h = head @ W2 + bias -> fp32
    gemm_tc<EPI_BIAS, false, false><<<dim3(DD / 128, MT / 128, 1), 256, SMEM_BYTES>>>(
        MT, DD, DD, he16, w2t16, hn, nullptr, bias, 0.f, 0, 0, 0);

    // LayerNorm -> fp16
    layernorm_kernel<<<MT, 256>>>(hn, nh);

    // t = swish(LN(h) @ wi) -> fp16
    gemm_tc<EPI_SWISH16, false, false><<<dim3(DD / 128, MT / 128, 1), 256, SMEM_BYTES>>>(
        MT, DD, DD, nh, wt16, nullptr, t16, nullptr, 0.f, 0, 0, 0);

    // out = t @ wi -> fp32
    gemm_tc<EPI_F32, false, false><<<dim3(DD / 128, MT / 128, 1), 256, SMEM_BYTES>>>(
        MT, DD, DD, t16, wt16, out, nullptr, nullptr, 0.f, 0, 0, 0);
}